// round 13
// baseline (speedup 1.0000x reference)
#include <cuda_runtime.h>
#include <cuda_fp16.h>
#include <cstdint>

#define NE 8
#define DD 1024
#define FF 4096
#define GG 2048

// ------------------------------ scratch (allocation-guard-safe) -------------
static __device__ __half g_xh [(size_t)NE * GG * DD];  // x fp16
static __device__ __half g_w1h[(size_t)NE * FF * DD];  // w_in^T  [e][F][D] fp16
static __device__ __half g_w2h[(size_t)NE * FF * DD];  // w_swiglu^T
static __device__ __half g_w3h[(size_t)NE * DD * FF];  // w_out^T [e][D][F]
static __device__ __half g_h  [(size_t)NE * GG * FF];  // hidden fp16

// ------------------------------ helpers -------------------------------------
__device__ __forceinline__ uint32_t smem_u32(const void* p) {
    uint32_t a;
    asm("{ .reg .u64 t; cvta.to.shared.u64 t, %1; cvt.u32.u64 %0, t; }" : "=r"(a) : "l"(p));
    return a;
}

// Tile row = 32 fp16 (64B), 16B chunks c=0..3, XOR swizzle c' = c ^ ((row>>1)&3):
// conflict-free for both cp.async stores and ldmatrix 8-row phases.
__device__ __forceinline__ uint32_t tileoff(int row, int c) {
    return (uint32_t)((row << 6) + (((c ^ ((row >> 1) & 3))) << 4));
}

#define CP_ASYNC(dst, src) \
    asm volatile("cp.async.cg.shared.global [%0], [%1], 16;" :: "r"(dst), "l"(src) : "memory")
#define CP_COMMIT() asm volatile("cp.async.commit_group;" ::: "memory")
#define CP_WAIT0()  asm volatile("cp.async.wait_group 0;" ::: "memory")
#define CP_WAIT1()  asm volatile("cp.async.wait_group 1;" ::: "memory")
#define CP_WAIT2()  asm volatile("cp.async.wait_group 2;" ::: "memory")

#define LDSM4(r, addr) \
    asm volatile("ldmatrix.sync.aligned.m8n8.x4.shared.b16 {%0,%1,%2,%3}, [%4];" \
                 : "=r"((r)[0]), "=r"((r)[1]), "=r"((r)[2]), "=r"((r)[3]) : "r"(addr))

#define MMA(c, a, b) \
    asm volatile("mma.sync.aligned.m16n8k16.row.col.f32.f16.f16.f32 " \
                 "{%0,%1,%2,%3}, {%4,%5,%6,%7}, {%8,%9}, {%0,%1,%2,%3};" \
                 : "+f"((c)[0]), "+f"((c)[1]), "+f"((c)[2]), "+f"((c)[3]) \
                 : "r"((a)[0]), "r"((a)[1]), "r"((a)[2]), "r"((a)[3]), \
                   "r"((b)[0]), "r"((b)[1]))

// ============================================================================
// Fused GEMM1-pair + SwiGLU (pure fp16 operands):
//   mid = x @ w1^T ; gate = x @ w2^T ; h = silu(mid)*gate -> fp16
// CTA tile m128 x n128(per output), k-chunk 32, 3-stage cp.async pipeline.
// 8 warps 2(m)x4(n); warp tile m64 x n32 PER OUTPUT (8 LDSM : 32 MMA per phase).
// ============================================================================
#define FSTG 24576   // A(8K) B1(8K) B2(8K)
#define FUSED_SMEM (3 * FSTG)

__global__ __launch_bounds__(256)
void fused_gemm1_swiglu(const __half* __restrict__ A_g,
                        const __half* __restrict__ B1_g, const __half* __restrict__ B2_g,
                        __half* __restrict__ H_g)
{
    extern __shared__ char smem[];
    const uint32_t sb = smem_u32(smem);
    const int tid = threadIdx.x, wid = tid >> 5, lane = tid & 31;
    const int wm = wid >> 2, wn = wid & 3;   // 2 x 4 warp grid

    const long long e = blockIdx.z;
    const __half* A  = A_g  + e * (long long)GG * DD;
    const __half* B1 = B1_g + e * (long long)FF * DD;
    const __half* B2 = B2_g + e * (long long)FF * DD;
    __half* H = H_g + e * (long long)GG * FF;

    const int rowA0 = blockIdx.y * 128;
    const int colB0 = blockIdx.x * 128;

    float acc1[4][4][4], acc2[4][4][4];   // [mb][nb][frag]
    #pragma unroll
    for (int i = 0; i < 4; i++)
        #pragma unroll
        for (int j = 0; j < 4; j++)
            #pragma unroll
            for (int k = 0; k < 4; k++) { acc1[i][j][k] = 0.f; acc2[i][j][k] = 0.f; }

    const int nC = DD >> 5;

    auto load_stage = [&](int c, int s) {
        const uint32_t base = sb + s * FSTG;
        const int kc = c << 5;
        #pragma unroll
        for (int i = 0; i < 2; i++) {
            const int idx = tid + (i << 8);
            const int row = idx >> 2, ch = idx & 3;
            const uint32_t o = tileoff(row, ch);
            CP_ASYNC(base + o,         A  + (size_t)(rowA0 + row) * DD + kc + ch * 8);
            CP_ASYNC(base + 8192 + o,  B1 + (size_t)(colB0 + row) * DD + kc + ch * 8);
            CP_ASYNC(base + 16384 + o, B2 + (size_t)(colB0 + row) * DD + kc + ch * 8);
        }
        CP_COMMIT();
    };

    load_stage(0, 0);
    load_stage(1, 1);

    int s = 0;
    for (int c = 0; c < nC; c++) {
        if (c + 2 < nC) {
            int s2 = s + 2; if (s2 >= 3) s2 -= 3;
            load_stage(c + 2, s2);
            CP_WAIT2();
        } else if (c + 1 < nC) CP_WAIT1();
        else                   CP_WAIT0();
        __syncthreads();

        const uint32_t tb = sb + s * FSTG;

        #pragma unroll
        for (int ks = 0; ks < 2; ks++) {
            const int ch = ks * 2 + (lane >> 4);
            uint32_t ah[4][4], b1[4][2], b2[4][2];
            #pragma unroll
            for (int mb = 0; mb < 4; mb++) {
                const int row = wm * 64 + mb * 16 + (lane & 15);
                LDSM4(ah[mb], tb + tileoff(row, ch));
            }
            #pragma unroll
            for (int nb16 = 0; nb16 < 2; nb16++) {
                const int row = wn * 32 + nb16 * 16 + (lane & 15);
                const uint32_t o = tileoff(row, ch);
                uint32_t r[4];
                LDSM4(r, tb + 8192 + o);
                b1[nb16 * 2][0] = r[0]; b1[nb16 * 2][1] = r[2];
                b1[nb16 * 2 + 1][0] = r[1]; b1[nb16 * 2 + 1][1] = r[3];
                LDSM4(r, tb + 16384 + o);
                b2[nb16 * 2][0] = r[0]; b2[nb16 * 2][1] = r[2];
                b2[nb16 * 2 + 1][0] = r[1]; b2[nb16 * 2 + 1][1] = r[3];
            }
            #pragma unroll
            for (int mb = 0; mb < 4; mb++)
                #pragma unroll
                for (int nb = 0; nb < 4; nb++) {
                    MMA(acc1[mb][nb], ah[mb], b1[nb]);
                    MMA(acc2[mb][nb], ah[mb], b2[nb]);
                }
        }
        __syncthreads();
        if (++s == 3) s = 0;
    }

    // epilogue: h = silu(mid)*gate -> fp16
    #pragma unroll
    for (int mb = 0; mb < 4; mb++) {
        const int m0 = rowA0 + wm * 64 + mb * 16 + (lane >> 2);
        #pragma unroll
        for (int nb = 0; nb < 4; nb++) {
            const int n = colB0 + wn * 32 + nb * 8 + (lane & 3) * 2;
            #pragma unroll
            for (int half_i = 0; half_i < 2; half_i++) {
                const int m = m0 + half_i * 8;
                float md0 = acc1[mb][nb][half_i * 2 + 0], gt0 = acc2[mb][nb][half_i * 2 + 0];
                float md1 = acc1[mb][nb][half_i * 2 + 1], gt1 = acc2[mb][nb][half_i * 2 + 1];
                float h0 = md0 / (1.f + __expf(-md0)) * gt0;
                float h1 = md1 / (1.f + __expf(-md1)) * gt1;
                *reinterpret_cast<ushort2*>(&H[(size_t)m * FF + n]) =
                    make_ushort2(__half_as_ushort(__float2half(h0)),
                                 __half_as_ushort(__float2half(h1)));
            }
        }
    }
}

// ============================================================================
// GEMM2: C = A @ B^T ; A:[M,K] fp16, B:[N,K] fp16.
// CTA m128 x n256, k-chunk 32, 3-stage pipeline.
// 8 warps 2(m)x4(n); warp tile m64 x n64 (8 LDSM : 32 MMA per phase).
// ============================================================================
#define GSTG 24576   // A(8K) B(16K)
#define GEMM_SMEM (3 * GSTG)

__global__ __launch_bounds__(256)
void mma_gemm(const __half* __restrict__ A_g, const __half* __restrict__ B_g,
              float* __restrict__ Cg, int M, int N, int K,
              long long strA, long long strB, long long strC)
{
    extern __shared__ char smem[];
    const uint32_t sb = smem_u32(smem);
    const int tid = threadIdx.x, wid = tid >> 5, lane = tid & 31;
    const int wm = wid >> 2, wn = wid & 3;

    const __half* A = A_g + (long long)blockIdx.z * strA;
    const __half* B = B_g + (long long)blockIdx.z * strB;
    float* C = Cg + (long long)blockIdx.z * strC;

    const int rowA0 = blockIdx.y * 128;
    const int colB0 = blockIdx.x * 256;

    float acc[4][8][4];
    #pragma unroll
    for (int i = 0; i < 4; i++)
        #pragma unroll
        for (int j = 0; j < 8; j++)
            #pragma unroll
            for (int k = 0; k < 4; k++) acc[i][j][k] = 0.f;

    const int nC = K >> 5;

    auto load_stage = [&](int c, int s) {
        const uint32_t base = sb + s * GSTG;
        const int kc = c << 5;
        #pragma unroll
        for (int i = 0; i < 2; i++) {
            const int idx = tid + (i << 8);
            const int row = idx >> 2, ch = idx & 3;
            CP_ASYNC(base + tileoff(row, ch), A + (size_t)(rowA0 + row) * K + kc + ch * 8);
        }
        #pragma unroll
        for (int i = 0; i < 4; i++) {
            const int idx = tid + (i << 8);
            const int row = idx >> 2, ch = idx & 3;
            CP_ASYNC(base + 8192 + tileoff(row, ch), B + (size_t)(colB0 + row) * K + kc + ch * 8);
        }
        CP_COMMIT();
    };

    load_stage(0, 0);
    load_stage(1, 1);

    int s = 0;
    for (int c = 0; c < nC; c++) {
        if (c + 2 < nC) {
            int s2 = s + 2; if (s2 >= 3) s2 -= 3;
            load_stage(c + 2, s2);
            CP_WAIT2();
        } else if (c + 1 < nC) CP_WAIT1();
        else                   CP_WAIT0();
        __syncthreads();

        const uint32_t tb = sb + s * GSTG;

        #pragma unroll
        for (int ks = 0; ks < 2; ks++) {
            uint32_t ah[4][4], bh[8][2];
            const int ch = ks * 2 + (lane >> 4);
            #pragma unroll
            for (int mb = 0; mb < 4; mb++) {
                const int row = wm * 64 + mb * 16 + (lane & 15);
                LDSM4(ah[mb], tb + tileoff(row, ch));
            }
            #pragma unroll
            for (int nb16 = 0; nb16 < 4; nb16++) {
                const int row = wn * 64 + nb16 * 16 + (lane & 15);
                uint32_t r[4];
                LDSM4(r, tb + 8192 + tileoff(row, ch));
                bh[nb16 * 2][0] = r[0]; bh[nb16 * 2][1] = r[2];
                bh[nb16 * 2 + 1][0] = r[1]; bh[nb16 * 2 + 1][1] = r[3];
            }
            #pragma unroll
            for (int mb = 0; mb < 4; mb++)
                #pragma unroll
                for (int nb = 0; nb < 8; nb++)
                    MMA(acc[mb][nb], ah[mb], bh[nb]);
        }
        __syncthreads();
        if (++s == 3) s = 0;
    }

    #pragma unroll
    for (int mb = 0; mb < 4; mb++) {
        const int m = rowA0 + wm * 64 + mb * 16 + (lane >> 2);
        #pragma unroll
        for (int nb = 0; nb < 8; nb++) {
            const int n = colB0 + wn * 64 + nb * 8 + (lane & 3) * 2;
            *reinterpret_cast<float2*>(&C[(size_t)m * N + n]) =
                make_float2(acc[mb][nb][0], acc[mb][nb][1]);
            *reinterpret_cast<float2*>(&C[(size_t)(m + 8) * N + n]) =
                make_float2(acc[mb][nb][2], acc[mb][nb][3]);
        }
    }
}

// ------------------------------ conversion kernels --------------------------
__global__ __launch_bounds__(256)
void convert_f16_kernel(const float* __restrict__ in, __half* __restrict__ out, size_t n4)
{
    size_t i = (size_t)blockIdx.x * blockDim.x + threadIdx.x;
    if (i >= n4) return;
    float4 v = reinterpret_cast<const float4*>(in)[i];
    reinterpret_cast<ushort4*>(out)[i] =
        make_ushort4(__half_as_ushort(__float2half(v.x)), __half_as_ushort(__float2half(v.y)),
                     __half_as_ushort(__float2half(v.z)), __half_as_ushort(__float2half(v.w)));
}

// w [e][K][N] fp32 -> wT [e][N][K] fp16 (32x32 tiles)
__global__ __launch_bounds__(256)
void transpose_h_kernel(const float* __restrict__ w, __half* __restrict__ wT, int K, int N)
{
    __shared__ float t[32][33];
    const int e = blockIdx.z;
    const int n0 = blockIdx.x * 32, k0 = blockIdx.y * 32;
    const int tx = threadIdx.x, ty = threadIdx.y;   // (32, 8)
    const float* we = w + (size_t)e * K * N;
    #pragma unroll
    for (int j = 0; j < 4; j++)
        t[ty + 8 * j][tx] = we[(size_t)(k0 + ty + 8 * j) * N + n0 + tx];
    __syncthreads();
    __half* wo = wT + (size_t)e * N * K;
    #pragma unroll
    for (int j = 0; j < 4; j++)
        wo[(size_t)(n0 + ty + 8 * j) * K + k0 + tx] = __float2half(t[tx][ty + 8 * j]);
}

// ------------------------------ launch --------------------------------------
extern "C" void kernel_launch(void* const* d_in, const int* in_sizes, int n_in,
                              void* d_out, int out_size)
{
    const float* x    = (const float*)d_in[0];
    const float* win  = (const float*)d_in[1];
    const float* wsw  = (const float*)d_in[2];
    const float* wout = (const float*)d_in[3];
    float* out = (float*)d_out;

    __half *xh, *w1h, *w2h, *w3h, *h;
    cudaGetSymbolAddress((void**)&xh, g_xh);
    cudaGetSymbolAddress((void**)&w1h, g_w1h);  cudaGetSymbolAddress((void**)&w2h, g_w2h);
    cudaGetSymbolAddress((void**)&w3h, g_w3h);
    cudaGetSymbolAddress((void**)&h, g_h);

    cudaFuncSetAttribute(fused_gemm1_swiglu, cudaFuncAttributeMaxDynamicSharedMemorySize, FUSED_SMEM);
    cudaFuncSetAttribute(mma_gemm, cudaFuncAttributeMaxDynamicSharedMemorySize, GEMM_SMEM);

    // 1) convert x to fp16
    {
        size_t n4 = (size_t)NE * GG * DD / 4;
        convert_f16_kernel<<<(unsigned)((n4 + 255) / 256), 256>>>(x, xh, n4);
    }
    // 2) transpose weights to [N,K] fp16
    {
        dim3 blk(32, 8);
        transpose_h_kernel<<<dim3(FF / 32, DD / 32, NE), blk>>>(win,  w1h, DD, FF);
        transpose_h_kernel<<<dim3(FF / 32, DD / 32, NE), blk>>>(wsw,  w2h, DD, FF);
        transpose_h_kernel<<<dim3(DD / 32, FF / 32, NE), blk>>>(wout, w3h, FF, DD);
    }
    // 3) fused GEMM1 pair + SwiGLU -> hidden fp16
    {
        dim3 grid(FF / 128, GG / 128, NE);
        fused_gemm1_swiglu<<<grid, 256, FUSED_SMEM>>>(xh, w1h, w2h, h);
    }
    // 4) GEMM2: [G,F] @ [D,F]^T -> [G,D]
    {
        dim3 grid(DD / 256, GG / 128, NE);
        mma_gemm<<<grid, 256, GEMM_SMEM>>>(h, w3h, out, GG, DD, FF,
                                           (long long)GG * FF, (long long)FF * DD, (long long)GG * DD);
    }
}

// round 16
// speedup vs baseline: 1.1870x; 1.1870x over previous
#include <cuda_runtime.h>
#include <cuda_fp16.h>
#include <cstdint>

#define NE 8
#define DD 1024
#define FF 4096
#define GG 2048

// ------------------------------ scratch (allocation-guard-safe) -------------
static __device__ __half g_xh [(size_t)NE * GG * DD];  // x fp16
static __device__ __half g_w1h[(size_t)NE * FF * DD];  // w_in^T  [e][F][D] fp16
static __device__ __half g_w2h[(size_t)NE * FF * DD];  // w_swiglu^T
static __device__ __half g_w3h[(size_t)NE * DD * FF];  // w_out^T [e][D][F]
static __device__ __half g_h  [(size_t)NE * GG * FF];  // hidden fp16

// ------------------------------ helpers -------------------------------------
__device__ __forceinline__ uint32_t smem_u32(const void* p) {
    uint32_t a;
    asm("{ .reg .u64 t; cvta.to.shared.u64 t, %1; cvt.u32.u64 %0, t; }" : "=r"(a) : "l"(p));
    return a;
}

// Tile row = 32 fp16 (64B), 16B chunks c=0..3, XOR swizzle c' = c ^ ((row>>1)&3):
// conflict-free for both cp.async stores and ldmatrix 8-row phases.
__device__ __forceinline__ uint32_t tileoff(int row, int c) {
    return (uint32_t)((row << 6) + (((c ^ ((row >> 1) & 3))) << 4));
}

#define CP_ASYNC(dst, src) \
    asm volatile("cp.async.cg.shared.global [%0], [%1], 16;" :: "r"(dst), "l"(src) : "memory")
#define CP_COMMIT() asm volatile("cp.async.commit_group;" ::: "memory")
#define CP_WAIT0()  asm volatile("cp.async.wait_group 0;" ::: "memory")
#define CP_WAIT1()  asm volatile("cp.async.wait_group 1;" ::: "memory")
#define CP_WAIT2()  asm volatile("cp.async.wait_group 2;" ::: "memory")

#define LDSM4(r, addr) \
    asm volatile("ldmatrix.sync.aligned.m8n8.x4.shared.b16 {%0,%1,%2,%3}, [%4];" \
                 : "=r"((r)[0]), "=r"((r)[1]), "=r"((r)[2]), "=r"((r)[3]) : "r"(addr))

#define MMA(c, a, b) \
    asm volatile("mma.sync.aligned.m16n8k16.row.col.f32.f16.f16.f32 " \
                 "{%0,%1,%2,%3}, {%4,%5,%6,%7}, {%8,%9}, {%0,%1,%2,%3};" \
                 : "+f"((c)[0]), "+f"((c)[1]), "+f"((c)[2]), "+f"((c)[3]) \
                 : "r"((a)[0]), "r"((a)[1]), "r"((a)[2]), "r"((a)[3]), \
                   "r"((b)[0]), "r"((b)[1]))

// ============================================================================
// Fused GEMM1-pair + SwiGLU (pure fp16 operands):
//   mid = x @ w1^T ; gate = x @ w2^T ; h = silu(mid)*gate -> fp16
// CTA tile m128 x n64, k-chunk 32, 3-stage cp.async pipeline.
// 8 warps 4(m)x2(n); warp tile m32 x n32 per output. Occupancy forced to 2.
// ============================================================================
#define FSTG 16384   // A(8K) B1(4K) B2(4K)
#define FUSED_SMEM (3 * FSTG)

__global__ __launch_bounds__(256, 2)
void fused_gemm1_swiglu(const __half* __restrict__ A_g,
                        const __half* __restrict__ B1_g, const __half* __restrict__ B2_g,
                        __half* __restrict__ H_g)
{
    extern __shared__ char smem[];
    const uint32_t sb = smem_u32(smem);
    const int tid = threadIdx.x, wid = tid >> 5, lane = tid & 31;
    const int wm = wid >> 1, wn = wid & 1;   // 4 x 2 warp grid

    const long long e = blockIdx.z;
    const __half* A  = A_g  + e * (long long)GG * DD;
    const __half* B1 = B1_g + e * (long long)FF * DD;
    const __half* B2 = B2_g + e * (long long)FF * DD;
    __half* H = H_g + e * (long long)GG * FF;

    const int rowA0 = blockIdx.y * 128;
    const int colB0 = blockIdx.x * 64;

    float acc1[2][4][4], acc2[2][4][4];
    #pragma unroll
    for (int i = 0; i < 2; i++)
        #pragma unroll
        for (int j = 0; j < 4; j++)
            #pragma unroll
            for (int k = 0; k < 4; k++) { acc1[i][j][k] = 0.f; acc2[i][j][k] = 0.f; }

    const int nC = DD >> 5;

    auto load_stage = [&](int c, int s) {
        const uint32_t base = sb + s * FSTG;
        const int kc = c << 5;
        #pragma unroll
        for (int i = 0; i < 2; i++) {
            const int idx = tid + (i << 8);
            const int row = idx >> 2, ch = idx & 3;
            CP_ASYNC(base + tileoff(row, ch), A + (size_t)(rowA0 + row) * DD + kc + ch * 8);
        }
        {
            const int row = tid >> 2, ch = tid & 3;
            const uint32_t o = tileoff(row, ch);
            const size_t g = (size_t)(colB0 + row) * DD + kc + ch * 8;
            CP_ASYNC(base + 8192 + o,  B1 + g);
            CP_ASYNC(base + 12288 + o, B2 + g);
        }
        CP_COMMIT();
    };

    load_stage(0, 0);
    load_stage(1, 1);

    int s = 0;
    for (int c = 0; c < nC; c++) {
        if (c + 2 < nC) {
            int s2 = s + 2; if (s2 >= 3) s2 -= 3;
            load_stage(c + 2, s2);
            CP_WAIT2();
        } else if (c + 1 < nC) CP_WAIT1();
        else                   CP_WAIT0();
        __syncthreads();

        const uint32_t tb = sb + s * FSTG;

        #pragma unroll
        for (int ks = 0; ks < 2; ks++) {
            const int ch = ks * 2 + (lane >> 4);
            uint32_t ah[2][4], b1[4][2], b2[4][2];
            #pragma unroll
            for (int mb = 0; mb < 2; mb++) {
                const int row = wm * 32 + mb * 16 + (lane & 15);
                LDSM4(ah[mb], tb + tileoff(row, ch));
            }
            #pragma unroll
            for (int nb16 = 0; nb16 < 2; nb16++) {
                const int row = wn * 32 + nb16 * 16 + (lane & 15);
                const uint32_t o = tileoff(row, ch);
                uint32_t r[4];
                LDSM4(r, tb + 8192 + o);
                b1[nb16 * 2][0] = r[0]; b1[nb16 * 2][1] = r[2];
                b1[nb16 * 2 + 1][0] = r[1]; b1[nb16 * 2 + 1][1] = r[3];
                LDSM4(r, tb + 12288 + o);
                b2[nb16 * 2][0] = r[0]; b2[nb16 * 2][1] = r[2];
                b2[nb16 * 2 + 1][0] = r[1]; b2[nb16 * 2 + 1][1] = r[3];
            }
            #pragma unroll
            for (int mb = 0; mb < 2; mb++)
                #pragma unroll
                for (int nb = 0; nb < 4; nb++) {
                    MMA(acc1[mb][nb], ah[mb], b1[nb]);
                    MMA(acc2[mb][nb], ah[mb], b2[nb]);
                }
        }
        __syncthreads();
        if (++s == 3) s = 0;
    }

    // epilogue: h = silu(mid)*gate -> fp16
    #pragma unroll
    for (int mb = 0; mb < 2; mb++) {
        const int m0 = rowA0 + wm * 32 + mb * 16 + (lane >> 2);
        #pragma unroll
        for (int nb = 0; nb < 4; nb++) {
            const int n = colB0 + wn * 32 + nb * 8 + (lane & 3) * 2;
            #pragma unroll
            for (int half_i = 0; half_i < 2; half_i++) {
                const int m = m0 + half_i * 8;
                float md0 = acc1[mb][nb][half_i * 2 + 0], gt0 = acc2[mb][nb][half_i * 2 + 0];
                float md1 = acc1[mb][nb][half_i * 2 + 1], gt1 = acc2[mb][nb][half_i * 2 + 1];
                float h0 = md0 / (1.f + __expf(-md0)) * gt0;
                float h1 = md1 / (1.f + __expf(-md1)) * gt1;
                *reinterpret_cast<ushort2*>(&H[(size_t)m * FF + n]) =
                    make_ushort2(__half_as_ushort(__float2half(h0)),
                                 __half_as_ushort(__float2half(h1)));
            }
        }
    }
}

// ============================================================================
// GEMM2: C = A @ B^T ; A:[M,K] fp16, B:[N,K] fp16.
// 128x128x32 CTA tile, 3-stage pipeline, 8 warps 2(m)x4(n), warp m64xn32.
// Occupancy forced to 2.
// ============================================================================
#define GSTG 16384   // A(8K) B(8K)
#define GEMM_SMEM (3 * GSTG)

__global__ __launch_bounds__(256, 2)
void mma_gemm(const __half* __restrict__ A_g, const __half* __restrict__ B_g,
              float* __restrict__ Cg, int M, int N, int K,
              long long strA, long long strB, long long strC)
{
    extern __shared__ char smem[];
    const uint32_t sb = smem_u32(smem);
    const int tid = threadIdx.x, wid = tid >> 5, lane = tid & 31;
    const int wm = wid >> 2, wn = wid & 3;

    const __half* A = A_g + (long long)blockIdx.z * strA;
    const __half* B = B_g + (long long)blockIdx.z * strB;
    float* C = Cg + (long long)blockIdx.z * strC;

    const int rowA0 = blockIdx.y * 128;
    const int colB0 = blockIdx.x * 128;

    float acc[4][4][4];
    #pragma unroll
    for (int i = 0; i < 4; i++)
        #pragma unroll
        for (int j = 0; j < 4; j++)
            #pragma unroll
            for (int k = 0; k < 4; k++) acc[i][j][k] = 0.f;

    const int nC = K >> 5;

    auto load_stage = [&](int c, int s) {
        const uint32_t base = sb + s * GSTG;
        const int kc = c << 5;
        #pragma unroll
        for (int i = 0; i < 2; i++) {
            const int idx = tid + (i << 8);
            const int row = idx >> 2, ch = idx & 3;
            const uint32_t o = tileoff(row, ch);
            CP_ASYNC(base + o,        A + (size_t)(rowA0 + row) * K + kc + ch * 8);
            CP_ASYNC(base + 8192 + o, B + (size_t)(colB0 + row) * K + kc + ch * 8);
        }
        CP_COMMIT();
    };

    load_stage(0, 0);
    load_stage(1, 1);

    int s = 0;
    for (int c = 0; c < nC; c++) {
        if (c + 2 < nC) {
            int s2 = s + 2; if (s2 >= 3) s2 -= 3;
            load_stage(c + 2, s2);
            CP_WAIT2();
        } else if (c + 1 < nC) CP_WAIT1();
        else                   CP_WAIT0();
        __syncthreads();

        const uint32_t tb = sb + s * GSTG;

        #pragma unroll
        for (int ks = 0; ks < 2; ks++) {
            uint32_t ah[4][4], bh[4][2];
            const int ch = ks * 2 + (lane >> 4);
            #pragma unroll
            for (int mb = 0; mb < 4; mb++) {
                const int row = wm * 64 + mb * 16 + (lane & 15);
                LDSM4(ah[mb], tb + tileoff(row, ch));
            }
            #pragma unroll
            for (int nb16 = 0; nb16 < 2; nb16++) {
                const int row = wn * 32 + nb16 * 16 + (lane & 15);
                uint32_t r[4];
                LDSM4(r, tb + 8192 + tileoff(row, ch));
                bh[nb16 * 2][0] = r[0]; bh[nb16 * 2][1] = r[2];
                bh[nb16 * 2 + 1][0] = r[1]; bh[nb16 * 2 + 1][1] = r[3];
            }
            #pragma unroll
            for (int mb = 0; mb < 4; mb++)
                #pragma unroll
                for (int nb = 0; nb < 4; nb++)
                    MMA(acc[mb][nb], ah[mb], bh[nb]);
        }
        __syncthreads();
        if (++s == 3) s = 0;
    }

    #pragma unroll
    for (int mb = 0; mb < 4; mb++) {
        const int m = rowA0 + wm * 64 + mb * 16 + (lane >> 2);
        #pragma unroll
        for (int nb = 0; nb < 4; nb++) {
            const int n = colB0 + wn * 32 + nb * 8 + (lane & 3) * 2;
            *reinterpret_cast<float2*>(&C[(size_t)m * N + n]) =
                make_float2(acc[mb][nb][0], acc[mb][nb][1]);
            *reinterpret_cast<float2*>(&C[(size_t)(m + 8) * N + n]) =
                make_float2(acc[mb][nb][2], acc[mb][nb][3]);
        }
    }
}

// ------------------------------ conversion kernels --------------------------
__global__ __launch_bounds__(256)
void convert_f16_kernel(const float* __restrict__ in, __half* __restrict__ out, size_t n4)
{
    size_t i = (size_t)blockIdx.x * blockDim.x + threadIdx.x;
    if (i >= n4) return;
    float4 v = reinterpret_cast<const float4*>(in)[i];
    reinterpret_cast<ushort4*>(out)[i] =
        make_ushort4(__half_as_ushort(__float2half(v.x)), __half_as_ushort(__float2half(v.y)),
                     __half_as_ushort(__float2half(v.z)), __half_as_ushort(__float2half(v.w)));
}

// w [e][K][N] fp32 -> wT [e][N][K] fp16 (32x32 tiles)
__global__ __launch_bounds__(256)
void transpose_h_kernel(const float* __restrict__ w, __half* __restrict__ wT, int K, int N)
{
    __shared__ float t[32][33];
    const int e = blockIdx.z;
    const int n0 = blockIdx.x * 32, k0 = blockIdx.y * 32;
    const int tx = threadIdx.x, ty = threadIdx.y;   // (32, 8)
    const float* we = w + (size_t)e * K * N;
    #pragma unroll
    for (int j = 0; j < 4; j++)
        t[ty + 8 * j][tx] = we[(size_t)(k0 + ty + 8 * j) * N + n0 + tx];
    __syncthreads();
    __half* wo = wT + (size_t)e * N * K;
    #pragma unroll
    for (int j = 0; j < 4; j++)
        wo[(size_t)(n0 + ty + 8 * j) * K + k0 + tx] = __float2half(t[tx][ty + 8 * j]);
}

// ------------------------------ launch --------------------------------------
extern "C" void kernel_launch(void* const* d_in, const int* in_sizes, int n_in,
                              void* d_out, int out_size)
{
    const float* x    = (const float*)d_in[0];
    const float* win  = (const float*)d_in[1];
    const float* wsw  = (const float*)d_in[2];
    const float* wout = (const float*)d_in[3];
    float* out = (float*)d_out;

    __half *xh, *w1h, *w2h, *w3h, *h;
    cudaGetSymbolAddress((void**)&xh, g_xh);
    cudaGetSymbolAddress((void**)&w1h, g_w1h);  cudaGetSymbolAddress((void**)&w2h, g_w2h);
    cudaGetSymbolAddress((void**)&w3h, g_w3h);
    cudaGetSymbolAddress((void**)&h, g_h);

    cudaFuncSetAttribute(fused_gemm1_swiglu, cudaFuncAttributeMaxDynamicSharedMemorySize, FUSED_SMEM);
    cudaFuncSetAttribute(mma_gemm, cudaFuncAttributeMaxDynamicSharedMemorySize, GEMM_SMEM);

    // 1) convert x to fp16
    {
        size_t n4 = (size_t)NE * GG * DD / 4;
        convert_f16_kernel<<<(unsigned)((n4 + 255) / 256), 256>>>(x, xh, n4);
    }
    // 2) transpose weights to [N,K] fp16
    {
        dim3 blk(32, 8);
        transpose_h_kernel<<<dim3(FF / 32, DD / 32, NE), blk>>>(win,  w1h, DD, FF);
        transpose_h_kernel<<<dim3(FF / 32, DD / 32, NE), blk>>>(wsw,  w2h, DD, FF);
        transpose_h_kernel<<<dim3(DD / 32, FF / 32, NE), blk>>>(wout, w3h, FF, DD);
    }
    // 3) fused GEMM1 pair + SwiGLU -> hidden fp16
    {
        dim3 grid(FF / 64, GG / 128, NE);
        fused_gemm1_swiglu<<<grid, 256, FUSED_SMEM>>>(xh, w1h, w2h, h);
    }
    // 4) GEMM2: [G,F] @ [D,F]^T -> [G,D]
    {
        dim3 grid(DD / 128, GG / 128, NE);
        mma_gemm<<<grid, 256, GEMM_SMEM>>>(h, w3h, out, GG, DD, FF,
                                           (long long)GG * FF, (long long)FF * DD, (long long)GG * DD);
    }
}

// round 17
// speedup vs baseline: 1.3586x; 1.1446x over previous
#include <cuda_runtime.h>
#include <cuda_fp16.h>
#include <cstdint>

#define NE 8
#define DD 1024
#define FF 4096
#define GG 2048

// ------------------------------ scratch (allocation-guard-safe) -------------
static __device__ __half g_xh [(size_t)NE * GG * DD];  // x fp16
static __device__ __half g_w1h[(size_t)NE * FF * DD];  // w_in^T  [e][F][D] fp16
static __device__ __half g_w2h[(size_t)NE * FF * DD];  // w_swiglu^T
static __device__ __half g_w3h[(size_t)NE * DD * FF];  // w_out^T [e][D][F]
static __device__ __half g_h  [(size_t)NE * GG * FF];  // hidden fp16

// ------------------------------ helpers -------------------------------------
__device__ __forceinline__ uint32_t smem_u32(const void* p) {
    uint32_t a;
    asm("{ .reg .u64 t; cvta.to.shared.u64 t, %1; cvt.u32.u64 %0, t; }" : "=r"(a) : "l"(p));
    return a;
}

// 64-wide k-chunk tile: row = 64 fp16 (128B), 16B chunks c=0..7,
// swizzle c' = c ^ (row & 7): conflict-free cp.async stores and
// conflict-free 8-row ldmatrix phases (distinct 16B slots per row group).
__device__ __forceinline__ uint32_t tileoff64(int row, int c) {
    return (uint32_t)((row << 7) + ((c ^ (row & 7)) << 4));
}

#define CP_ASYNC(dst, src) \
    asm volatile("cp.async.cg.shared.global [%0], [%1], 16;" :: "r"(dst), "l"(src) : "memory")
#define CP_COMMIT() asm volatile("cp.async.commit_group;" ::: "memory")
#define CP_WAIT0()  asm volatile("cp.async.wait_group 0;" ::: "memory")
#define CP_WAIT1()  asm volatile("cp.async.wait_group 1;" ::: "memory")
#define CP_WAIT2()  asm volatile("cp.async.wait_group 2;" ::: "memory")

#define LDSM4(r, addr) \
    asm volatile("ldmatrix.sync.aligned.m8n8.x4.shared.b16 {%0,%1,%2,%3}, [%4];" \
                 : "=r"((r)[0]), "=r"((r)[1]), "=r"((r)[2]), "=r"((r)[3]) : "r"(addr))

#define MMA(c, a, b) \
    asm volatile("mma.sync.aligned.m16n8k16.row.col.f32.f16.f16.f32 " \
                 "{%0,%1,%2,%3}, {%4,%5,%6,%7}, {%8,%9}, {%0,%1,%2,%3};" \
                 : "+f"((c)[0]), "+f"((c)[1]), "+f"((c)[2]), "+f"((c)[3]) \
                 : "r"((a)[0]), "r"((a)[1]), "r"((a)[2]), "r"((a)[3]), \
                   "r"((b)[0]), "r"((b)[1]))

// ============================================================================
// Fused GEMM1-pair + SwiGLU (pure fp16):
//   mid = x @ w1^T ; gate = x @ w2^T ; h = silu(mid)*gate -> fp16
// CTA m128 x n64, k-chunk 64, 3-stage cp.async pipeline, occupancy 2.
// 8 warps 4(m)x2(n); warp tile m32 x n32 per output.
// ============================================================================
#define FSTG 32768   // A(16K) B1(8K) B2(8K)
#define FUSED_SMEM (3 * FSTG)

__global__ __launch_bounds__(256, 2)
void fused_gemm1_swiglu(const __half* __restrict__ A_g,
                        const __half* __restrict__ B1_g, const __half* __restrict__ B2_g,
                        __half* __restrict__ H_g)
{
    extern __shared__ char smem[];
    const uint32_t sb = smem_u32(smem);
    const int tid = threadIdx.x, wid = tid >> 5, lane = tid & 31;
    const int wm = wid >> 1, wn = wid & 1;   // 4 x 2 warp grid

    const long long e = blockIdx.z;
    const __half* A  = A_g  + e * (long long)GG * DD;
    const __half* B1 = B1_g + e * (long long)FF * DD;
    const __half* B2 = B2_g + e * (long long)FF * DD;
    __half* H = H_g + e * (long long)GG * FF;

    const int rowA0 = blockIdx.y * 128;
    const int colB0 = blockIdx.x * 64;

    float acc1[2][4][4], acc2[2][4][4];
    #pragma unroll
    for (int i = 0; i < 2; i++)
        #pragma unroll
        for (int j = 0; j < 4; j++)
            #pragma unroll
            for (int k = 0; k < 4; k++) { acc1[i][j][k] = 0.f; acc2[i][j][k] = 0.f; }

    const int nC = DD >> 6;   // 16 chunks

    auto load_stage = [&](int c, int s) {
        const uint32_t base = sb + s * FSTG;
        const int kc = c << 6;
        #pragma unroll
        for (int i = 0; i < 4; i++) {
            const int idx = tid + (i << 8);
            const int row = idx >> 3, ch = idx & 7;
            CP_ASYNC(base + tileoff64(row, ch), A + (size_t)(rowA0 + row) * DD + kc + ch * 8);
        }
        #pragma unroll
        for (int i = 0; i < 2; i++) {
            const int idx = tid + (i << 8);
            const int row = idx >> 3, ch = idx & 7;
            const uint32_t o = tileoff64(row, ch);
            const size_t g = (size_t)(colB0 + row) * DD + kc + ch * 8;
            CP_ASYNC(base + 16384 + o, B1 + g);
            CP_ASYNC(base + 24576 + o, B2 + g);
        }
        CP_COMMIT();
    };

    load_stage(0, 0);
    load_stage(1, 1);

    int s = 0;
    for (int c = 0; c < nC; c++) {
        if (c + 2 < nC) {
            int s2 = s + 2; if (s2 >= 3) s2 -= 3;
            load_stage(c + 2, s2);
            CP_WAIT2();
        } else if (c + 1 < nC) CP_WAIT1();
        else                   CP_WAIT0();
        __syncthreads();

        const uint32_t tb = sb + s * FSTG;

        #pragma unroll
        for (int ks = 0; ks < 4; ks++) {
            const int ch = ks * 2 + (lane >> 4);
            uint32_t ah[2][4], b1[4][2], b2[4][2];
            #pragma unroll
            for (int mb = 0; mb < 2; mb++) {
                const int row = wm * 32 + mb * 16 + (lane & 15);
                LDSM4(ah[mb], tb + tileoff64(row, ch));
            }
            #pragma unroll
            for (int nb16 = 0; nb16 < 2; nb16++) {
                const int row = wn * 32 + nb16 * 16 + (lane & 15);
                const uint32_t o = tileoff64(row, ch);
                uint32_t r[4];
                LDSM4(r, tb + 16384 + o);
                b1[nb16 * 2][0] = r[0]; b1[nb16 * 2][1] = r[2];
                b1[nb16 * 2 + 1][0] = r[1]; b1[nb16 * 2 + 1][1] = r[3];
                LDSM4(r, tb + 24576 + o);
                b2[nb16 * 2][0] = r[0]; b2[nb16 * 2][1] = r[2];
                b2[nb16 * 2 + 1][0] = r[1]; b2[nb16 * 2 + 1][1] = r[3];
            }
            #pragma unroll
            for (int mb = 0; mb < 2; mb++)
                #pragma unroll
                for (int nb = 0; nb < 4; nb++) {
                    MMA(acc1[mb][nb], ah[mb], b1[nb]);
                    MMA(acc2[mb][nb], ah[mb], b2[nb]);
                }
        }
        __syncthreads();
        if (++s == 3) s = 0;
    }

    // epilogue: h = silu(mid)*gate -> fp16
    #pragma unroll
    for (int mb = 0; mb < 2; mb++) {
        const int m0 = rowA0 + wm * 32 + mb * 16 + (lane >> 2);
        #pragma unroll
        for (int nb = 0; nb < 4; nb++) {
            const int n = colB0 + wn * 32 + nb * 8 + (lane & 3) * 2;
            #pragma unroll
            for (int half_i = 0; half_i < 2; half_i++) {
                const int m = m0 + half_i * 8;
                float md0 = acc1[mb][nb][half_i * 2 + 0], gt0 = acc2[mb][nb][half_i * 2 + 0];
                float md1 = acc1[mb][nb][half_i * 2 + 1], gt1 = acc2[mb][nb][half_i * 2 + 1];
                float h0 = md0 / (1.f + __expf(-md0)) * gt0;
                float h1 = md1 / (1.f + __expf(-md1)) * gt1;
                *reinterpret_cast<ushort2*>(&H[(size_t)m * FF + n]) =
                    make_ushort2(__half_as_ushort(__float2half(h0)),
                                 __half_as_ushort(__float2half(h1)));
            }
        }
    }
}

// ============================================================================
// GEMM2: C = A @ B^T ; A:[M,K] fp16, B:[N,K] fp16.
// CTA m128 x n128, k-chunk 64, 3-stage pipeline, occupancy 2.
// 8 warps 2(m)x4(n); warp tile m64 x n32.
// ============================================================================
#define GSTG 32768   // A(16K) B(16K)
#define GEMM_SMEM (3 * GSTG)

__global__ __launch_bounds__(256, 2)
void mma_gemm(const __half* __restrict__ A_g, const __half* __restrict__ B_g,
              float* __restrict__ Cg, int M, int N, int K,
              long long strA, long long strB, long long strC)
{
    extern __shared__ char smem[];
    const uint32_t sb = smem_u32(smem);
    const int tid = threadIdx.x, wid = tid >> 5, lane = tid & 31;
    const int wm = wid >> 2, wn = wid & 3;

    const __half* A = A_g + (long long)blockIdx.z * strA;
    const __half* B = B_g + (long long)blockIdx.z * strB;
    float* C = Cg + (long long)blockIdx.z * strC;

    const int rowA0 = blockIdx.y * 128;
    const int colB0 = blockIdx.x * 128;

    float acc[4][4][4];
    #pragma unroll
    for (int i = 0; i < 4; i++)
        #pragma unroll
        for (int j = 0; j < 4; j++)
            #pragma unroll
            for (int k = 0; k < 4; k++) acc[i][j][k] = 0.f;

    const int nC = K >> 6;

    auto load_stage = [&](int c, int s) {
        const uint32_t base = sb + s * GSTG;
        const int kc = c << 6;
        #pragma unroll
        for (int i = 0; i < 4; i++) {
            const int idx = tid + (i << 8);
            const int row = idx >> 3, ch = idx & 7;
            const uint32_t o = tileoff64(row, ch);
            CP_ASYNC(base + o,         A + (size_t)(rowA0 + row) * K + kc + ch * 8);
            CP_ASYNC(base + 16384 + o, B + (size_t)(colB0 + row) * K + kc + ch * 8);
        }
        CP_COMMIT();
    };

    load_stage(0, 0);
    load_stage(1, 1);

    int s = 0;
    for (int c = 0; c < nC; c++) {
        if (c + 2 < nC) {
            int s2 = s + 2; if (s2 >= 3) s2 -= 3;
            load_stage(c + 2, s2);
            CP_WAIT2();
        } else if (c + 1 < nC) CP_WAIT1();
        else                   CP_WAIT0();
        __syncthreads();

        const uint32_t tb = sb + s * GSTG;

        #pragma unroll
        for (int ks = 0; ks < 4; ks++) {
            uint32_t ah[4][4], bh[4][2];
            const int ch = ks * 2 + (lane >> 4);
            #pragma unroll
            for (int mb = 0; mb < 4; mb++) {
                const int row = wm * 64 + mb * 16 + (lane & 15);
                LDSM4(ah[mb], tb + tileoff64(row, ch));
            }
            #pragma unroll
            for (int nb16 = 0; nb16 < 2; nb16++) {
                const int row = wn * 32 + nb16 * 16 + (lane & 15);
                uint32_t r[4];
                LDSM4(r, tb + 16384 + tileoff64(row, ch));
                bh[nb16 * 2][0] = r[0]; bh[nb16 * 2][1] = r[2];
                bh[nb16 * 2 + 1][0] = r[1]; bh[nb16 * 2 + 1][1] = r[3];
            }
            #pragma unroll
            for (int mb = 0; mb < 4; mb++)
                #pragma unroll
                for (int nb = 0; nb < 4; nb++)
                    MMA(acc[mb][nb], ah[mb], bh[nb]);
        }
        __syncthreads();
        if (++s == 3) s = 0;
    }

    #pragma unroll
    for (int mb = 0; mb < 4; mb++) {
        const int m = rowA0 + wm * 64 + mb * 16 + (lane >> 2);
        #pragma unroll
        for (int nb = 0; nb < 4; nb++) {
            const int n = colB0 + wn * 32 + nb * 8 + (lane & 3) * 2;
            *reinterpret_cast<float2*>(&C[(size_t)m * N + n]) =
                make_float2(acc[mb][nb][0], acc[mb][nb][1]);
            *reinterpret_cast<float2*>(&C[(size_t)(m + 8) * N + n]) =
                make_float2(acc[mb][nb][2], acc[mb][nb][3]);
        }
    }
}

// ------------------------------ conversion kernels --------------------------
__global__ __launch_bounds__(256)
void convert_f16_kernel(const float* __restrict__ in, __half* __restrict__ out, size_t n4)
{
    size_t i = (size_t)blockIdx.x * blockDim.x + threadIdx.x;
    if (i >= n4) return;
    float4 v = reinterpret_cast<const float4*>(in)[i];
    reinterpret_cast<ushort4*>(out)[i] =
        make_ushort4(__half_as_ushort(__float2half(v.x)), __half_as_ushort(__float2half(v.y)),
                     __half_as_ushort(__float2half(v.z)), __half_as_ushort(__float2half(v.w)));
}

// w [e][K][N] fp32 -> wT [e][N][K] fp16.  64k x 32n tiles, block (32,8).
// Coalesced fp32 reads; coalesced ushort2 (4B/thread) writes.
__global__ __launch_bounds__(256)
void transpose_h_kernel(const float* __restrict__ w, __half* __restrict__ wT, int K, int N)
{
    __shared__ float t[32][65];   // [n_local][k_local], stride 65: phase-1 conflict-free
    const int e = blockIdx.z;
    const int n0 = blockIdx.x * 32, k0 = blockIdx.y * 64;
    const int tx = threadIdx.x, ty = threadIdx.y;   // (32, 8)
    const float* we = w + (size_t)e * K * N;
    #pragma unroll
    for (int j = 0; j < 8; j++) {
        const int k = ty + 8 * j;
        t[tx][k] = we[(size_t)(k0 + k) * N + n0 + tx];
    }
    __syncthreads();
    __half* wo = wT + (size_t)e * N * K;
    #pragma unroll
    for (int j = 0; j < 4; j++) {
        const int nl = ty + 8 * j;
        const float v0 = t[nl][2 * tx], v1 = t[nl][2 * tx + 1];
        *reinterpret_cast<ushort2*>(&wo[(size_t)(n0 + nl) * K + k0 + 2 * tx]) =
            make_ushort2(__half_as_ushort(__float2half(v0)),
                         __half_as_ushort(__float2half(v1)));
    }
}

// ------------------------------ launch --------------------------------------
extern "C" void kernel_launch(void* const* d_in, const int* in_sizes, int n_in,
                              void* d_out, int out_size)
{
    const float* x    = (const float*)d_in[0];
    const float* win  = (const float*)d_in[1];
    const float* wsw  = (const float*)d_in[2];
    const float* wout = (const float*)d_in[3];
    float* out = (float*)d_out;

    __half *xh, *w1h, *w2h, *w3h, *h;
    cudaGetSymbolAddress((void**)&xh, g_xh);
    cudaGetSymbolAddress((void**)&w1h, g_w1h);  cudaGetSymbolAddress((void**)&w2h, g_w2h);
    cudaGetSymbolAddress((void**)&w3h, g_w3h);
    cudaGetSymbolAddress((void**)&h, g_h);

    cudaFuncSetAttribute(fused_gemm1_swiglu, cudaFuncAttributeMaxDynamicSharedMemorySize, FUSED_SMEM);
    cudaFuncSetAttribute(mma_gemm, cudaFuncAttributeMaxDynamicSharedMemorySize, GEMM_SMEM);

    // 1) convert x to fp16
    {
        size_t n4 = (size_t)NE * GG * DD / 4;
        convert_f16_kernel<<<(unsigned)((n4 + 255) / 256), 256>>>(x, xh, n4);
    }
    // 2) transpose weights to [N,K] fp16  (grid: N/32, K/64, E)
    {
        dim3 blk(32, 8);
        transpose_h_kernel<<<dim3(FF / 32, DD / 64, NE), blk>>>(win,  w1h, DD, FF);
        transpose_h_kernel<<<dim3(FF / 32, DD / 64, NE), blk>>>(wsw,  w2h, DD, FF);
        transpose_h_kernel<<<dim3(DD / 32, FF / 64, NE), blk>>>(wout, w3h, FF, DD);
    }
    // 3) fused GEMM1 pair + SwiGLU -> hidden fp16
    {
        dim3 grid(FF / 64, GG / 128, NE);
        fused_gemm1_swiglu<<<grid, 256, FUSED_SMEM>>>(xh, w1h, w2h, h);
    }
    // 4) GEMM2: [G,F] @ [D,F]^T -> [G,D]
    {
        dim3 grid(DD / 128, GG / 128, NE);
        mma_gemm<<<grid, 256, GEMM_SMEM>>>(h, w3h, out, GG, DD, FF,
                                           (long long)GG * FF, (long long)FF * DD, (long long)GG * DD);
    }
}